// round 2
// baseline (speedup 1.0000x reference)
#include <cuda_runtime.h>

#define NN 65536
#define EE 2097152
#define HID 32
#define NG 8
#define OC 33
#define ISZ 8192

// ---------------- scratch (static device allocations only) ----------------
__device__ int   g_deg[NN];
__device__ float g_dinv[NN];
__device__ int   g_cnt[NN];
__device__ int   g_rowptr[NN];
__device__ int   g_wp[NN];
__device__ int   g_bsum[64];
__device__ int2  g_edges[EE];          // x = src, y = float bits of norm
__device__ float g_s1[NN], g_s2[NN], g_s3[NN], g_s4[NN];
__device__ __align__(128) float g_H[NN * HID];
__device__ __align__(128) float g_A[NN * HID];
__device__ __align__(128) float g_B[NN * HID];
__device__ __align__(128) float g_C[NN * HID];
__device__ __align__(128) float g_O[NN * HID];

// ---------------- CSR build ----------------
__global__ void k_zero() {
    int i = blockIdx.x * blockDim.x + threadIdx.x;
    if (i < NN) { g_deg[i] = 0; g_cnt[i] = 0; }
}

__global__ void k_hist(const int* __restrict__ ei) {
    int e = blockIdx.x * blockDim.x + threadIdx.x;
    if (e < EE) {
        atomicAdd(&g_deg[ei[e]], 1);        // degree by src
        atomicAdd(&g_cnt[ei[EE + e]], 1);   // histogram by dst
    }
}

__global__ void k_dinv() {
    int i = blockIdx.x * blockDim.x + threadIdx.x;
    if (i < NN) {
        int d = g_deg[i];
        g_dinv[i] = (d > 0) ? rsqrtf((float)d) : 0.0f;
    }
}

// block-level inclusive scan of g_cnt (64 blocks x 1024)
__global__ void k_scan1() {
    __shared__ int wsum[32];
    int t = threadIdx.x, b = blockIdx.x;
    int i = b * 1024 + t;
    int lane = t & 31, w = t >> 5;
    int x = g_cnt[i];
    #pragma unroll
    for (int o = 1; o < 32; o <<= 1) {
        int y = __shfl_up_sync(0xffffffffu, x, o);
        if (lane >= o) x += y;
    }
    if (lane == 31) wsum[w] = x;
    __syncthreads();
    if (w == 0) {
        int s = wsum[lane];
        #pragma unroll
        for (int o = 1; o < 32; o <<= 1) {
            int y = __shfl_up_sync(0xffffffffu, s, o);
            if (lane >= o) s += y;
        }
        wsum[lane] = s;
    }
    __syncthreads();
    int incl = x + (w > 0 ? wsum[w - 1] : 0);
    g_rowptr[i] = incl;                 // inclusive-within-block (temp)
    if (t == 1023) g_bsum[b] = incl;
}

__global__ void k_scan2() {
    if (threadIdx.x == 0) {
        int s = 0;
        for (int b = 0; b < 64; b++) { int v = g_bsum[b]; g_bsum[b] = s; s += v; }
    }
}

__global__ void k_scan3() {
    int i = blockIdx.x * blockDim.x + threadIdx.x;
    if (i < NN) {
        int excl = g_rowptr[i] - g_cnt[i] + g_bsum[i >> 10];
        g_rowptr[i] = excl;
        g_wp[i] = excl;
    }
}

__global__ void k_scatter(const int* __restrict__ ei) {
    int e = blockIdx.x * blockDim.x + threadIdx.x;
    if (e < EE) {
        int s = ei[e], d = ei[EE + e];
        float nrm = -(g_dinv[s] * g_dinv[d]);
        int pos = atomicAdd(&g_wp[d], 1);
        g_edges[pos] = make_int2(s, __float_as_int(nrm));
    }
}

// ---------------- layer 1 (scalar features) ----------------
template <bool PREV>
__global__ void k_sprop(const float* __restrict__ sin,
                        const float* __restrict__ sprev,
                        float* __restrict__ sout) {
    int gw = (blockIdx.x * blockDim.x + threadIdx.x) >> 5;
    int lane = threadIdx.x & 31;
    int beg = g_rowptr[gw], c = g_cnt[gw];
    float acc = 0.0f;
    for (int j = lane; j < c; j += 32) {
        int2 ed = g_edges[beg + j];
        acc += __int_as_float(ed.y) * __ldg(&sin[ed.x]);
    }
    #pragma unroll
    for (int o = 16; o; o >>= 1) acc += __shfl_xor_sync(0xffffffffu, acc, o);
    if (lane == 0) sout[gw] = PREV ? (2.0f * acc - sprev[gw]) : acc;
}

__global__ void k_l1(const float* __restrict__ x, const float* __restrict__ W1,
                     const float* __restrict__ b1) {
    int i = blockIdx.x * blockDim.x + threadIdx.x;   // NN*HID threads
    int n = i >> 5, c = i & 31;
    float v = b1[c]
            + x[n]      * W1[c]
            + g_s1[n]   * W1[32 + c]
            + g_s2[n]   * W1[64 + c]
            + g_s3[n]   * W1[96 + c]
            + g_s4[n]   * W1[128 + c];
    g_H[i] = fmaxf(v, 0.0f);
}

// ---------------- layers 2/3 (32-wide) ----------------
// out = H @ W0  (warp per node, shfl-broadcast GEMM, W column in regs)
__global__ void __launch_bounds__(256) k_init32(const float* __restrict__ W0) {
    int gw = (blockIdx.x * blockDim.x + threadIdx.x) >> 5;
    int lane = threadIdx.x & 31;
    float Wc[32];
    #pragma unroll
    for (int j = 0; j < 32; j++) Wc[j] = __ldg(&W0[j * 32 + lane]);
    float h = g_H[gw * HID + lane];
    float acc = 0.0f;
    #pragma unroll
    for (int j = 0; j < 32; j++)
        acc = fmaf(__shfl_sync(0xffffffffu, h, j), Wc[j], acc);
    g_O[gw * HID + lane] = acc;
}

// fused: t_new = (PREV ? 2*prop(tin) - tprev : prop(tin));  tout = t_new;
//        g_O += t_new @ Wk
template <bool PREV>
__global__ void __launch_bounds__(256) k_prop32(const float* __restrict__ tin,
                                                const float* __restrict__ tprev,
                                                float* __restrict__ tout,
                                                const float* __restrict__ Wk) {
    int gw = (blockIdx.x * blockDim.x + threadIdx.x) >> 5;
    int lane = threadIdx.x & 31;
    float Wc[32];
    #pragma unroll
    for (int j = 0; j < 32; j++) Wc[j] = __ldg(&Wk[j * 32 + lane]);
    int beg = g_rowptr[gw], cnt = g_cnt[gw];
    float acc = 0.0f;
    for (int base = 0; base < cnt; base += 8) {
        #pragma unroll
        for (int jj = 0; jj < 8; jj++) {
            if (base + jj < cnt) {                       // uniform across warp
                int2 ed = g_edges[beg + base + jj];      // uniform (broadcast) load
                acc = fmaf(__int_as_float(ed.y),
                           __ldg(&tin[ed.x * HID + lane]), acc);
            }
        }
    }
    float tn = PREV ? (2.0f * acc - tprev[gw * HID + lane]) : acc;
    tout[gw * HID + lane] = tn;
    float oacc = g_O[gw * HID + lane];
    #pragma unroll
    for (int j = 0; j < 32; j++)
        oacc = fmaf(__shfl_sync(0xffffffffu, tn, j), Wc[j], oacc);
    g_O[gw * HID + lane] = oacc;
}

// H = act(O + b)
__global__ void k_finalize(const float* __restrict__ b, int relu) {
    int i = blockIdx.x * blockDim.x + threadIdx.x;
    float v = g_O[i] + b[i & 31];
    g_H[i] = relu ? fmaxf(v, 0.0f) : v;
}

// ---------------- final linear: (8, 262144) @ (262144, 33) + bl ----------------
__global__ void k_obias(const float* __restrict__ bl, float* __restrict__ out) {
    int i = threadIdx.x;
    if (i < NG * OC) out[i] = bl[i % OC];
}

__global__ void __launch_bounds__(288) k_linear(const float* __restrict__ Wl,
                                                float* __restrict__ out) {
    __shared__ float Ws[128 * OC];   // 16896 B
    __shared__ float hs[NG * 128];   //  4096 B
    int t = threadIdx.x;
    int i0 = blockIdx.x * 128;
    for (int j = t; j < 128 * OC; j += 288) Ws[j] = Wl[i0 * OC + j];
    for (int j = t; j < NG * 128; j += 288) {
        int g = j >> 7, ii = j & 127;
        hs[j] = g_H[g * (ISZ * HID) + i0 + ii];
    }
    __syncthreads();
    if (t < NG * OC) {
        int g = t / OC, o = t % OC;
        float acc = 0.0f;
        #pragma unroll 8
        for (int ii = 0; ii < 128; ii++)
            acc = fmaf(hs[g * 128 + ii], Ws[ii * OC + o], acc);
        atomicAdd(&out[g * OC + o], acc);
    }
}

// ---------------- host ----------------
extern "C" void kernel_launch(void* const* d_in, const int* in_sizes, int n_in,
                              void* d_out, int out_size) {
    const float* x  = (const float*)d_in[0];
    const int*   ei = (const int*)  d_in[1];
    const float* W1 = (const float*)d_in[3];
    const float* b1 = (const float*)d_in[4];
    const float* W2 = (const float*)d_in[5];
    const float* b2 = (const float*)d_in[6];
    const float* W3 = (const float*)d_in[7];
    const float* b3 = (const float*)d_in[8];
    const float* Wl = (const float*)d_in[9];
    const float* bl = (const float*)d_in[10];
    float* out = (float*)d_out;

    float *dH, *dA, *dB, *dC, *dS1, *dS2, *dS3, *dS4;
    cudaGetSymbolAddress((void**)&dH,  g_H);
    cudaGetSymbolAddress((void**)&dA,  g_A);
    cudaGetSymbolAddress((void**)&dB,  g_B);
    cudaGetSymbolAddress((void**)&dC,  g_C);
    cudaGetSymbolAddress((void**)&dS1, g_s1);
    cudaGetSymbolAddress((void**)&dS2, g_s2);
    cudaGetSymbolAddress((void**)&dS3, g_s3);
    cudaGetSymbolAddress((void**)&dS4, g_s4);

    // CSR build
    k_zero   <<<NN / 256, 256>>>();
    k_hist   <<<EE / 256, 256>>>(ei);
    k_dinv   <<<NN / 256, 256>>>();
    k_scan1  <<<64, 1024>>>();
    k_scan2  <<<1, 32>>>();
    k_scan3  <<<64, 1024>>>();
    k_scatter<<<EE / 256, 256>>>(ei);

    // layer 1 (scalar Chebyshev recurrence, then combine)
    k_sprop<false><<<NN / 8, 256>>>(x,   nullptr, dS1);
    k_sprop<true> <<<NN / 8, 256>>>(dS1, x,       dS2);
    k_sprop<true> <<<NN / 8, 256>>>(dS2, dS1,     dS3);
    k_sprop<true> <<<NN / 8, 256>>>(dS3, dS2,     dS4);
    k_l1<<<NN * HID / 256, 256>>>(x, W1, b1);

    // layer 2
    k_init32        <<<NN / 8, 256>>>(W2);
    k_prop32<false> <<<NN / 8, 256>>>(dH, nullptr, dA, W2 + 1 * 1024);
    k_prop32<true>  <<<NN / 8, 256>>>(dA, dH,      dB, W2 + 2 * 1024);
    k_prop32<true>  <<<NN / 8, 256>>>(dB, dA,      dC, W2 + 3 * 1024);
    k_prop32<true>  <<<NN / 8, 256>>>(dC, dB,      dA, W2 + 4 * 1024);
    k_finalize<<<NN * HID / 256, 256>>>(b2, 1);

    // layer 3
    k_init32        <<<NN / 8, 256>>>(W3);
    k_prop32<false> <<<NN / 8, 256>>>(dH, nullptr, dA, W3 + 1 * 1024);
    k_prop32<true>  <<<NN / 8, 256>>>(dA, dH,      dB, W3 + 2 * 1024);
    k_prop32<true>  <<<NN / 8, 256>>>(dB, dA,      dC, W3 + 3 * 1024);
    k_prop32<true>  <<<NN / 8, 256>>>(dC, dB,      dA, W3 + 4 * 1024);
    k_finalize<<<NN * HID / 256, 256>>>(b3, 0);

    // readout
    k_obias <<<1, 288>>>(bl, out);
    k_linear<<<(ISZ * HID) / 128, 288>>>(Wl, out);
}

// round 3
// speedup vs baseline: 1.1229x; 1.1229x over previous
#include <cuda_runtime.h>

#define NN 65536
#define EE 2097152
#define HID 32
#define NG 8
#define OC 33
#define ISZ 8192

// ---------------- scratch (static device allocations only) ----------------
__device__ int   g_deg[NN];
__device__ float g_dinv[NN];
__device__ int   g_cnt[NN];
__device__ int   g_rowptr[NN];
__device__ int   g_wp[NN];
__device__ int   g_bsum[64];
__device__ int2  g_edges[EE];          // x = src, y = float bits of norm
__device__ float g_s1[NN], g_s2[NN], g_s3[NN], g_s4[NN];
__device__ __align__(128) float g_H[NN * HID];
__device__ __align__(128) float g_A[NN * HID];
__device__ __align__(128) float g_B[NN * HID];
__device__ __align__(128) float g_C[NN * HID];
__device__ __align__(128) float g_O[NN * HID];

// ---------------- CSR build ----------------
__global__ void k_zero() {
    int i = blockIdx.x * blockDim.x + threadIdx.x;
    if (i < NN) { g_deg[i] = 0; g_cnt[i] = 0; }
}

__global__ void k_hist(const int* __restrict__ ei) {
    int e = blockIdx.x * blockDim.x + threadIdx.x;
    if (e < EE) {
        atomicAdd(&g_deg[ei[e]], 1);        // degree by src
        atomicAdd(&g_cnt[ei[EE + e]], 1);   // histogram by dst
    }
}

// block-level inclusive scan of g_cnt (64 blocks x 1024) + fused dinv
__global__ void k_scan1() {
    __shared__ int wsum[32];
    int t = threadIdx.x, b = blockIdx.x;
    int i = b * 1024 + t;
    int lane = t & 31, w = t >> 5;
    // fused dinv (g_deg is final after k_hist)
    int d = g_deg[i];
    g_dinv[i] = (d > 0) ? rsqrtf((float)d) : 0.0f;

    int x = g_cnt[i];
    #pragma unroll
    for (int o = 1; o < 32; o <<= 1) {
        int y = __shfl_up_sync(0xffffffffu, x, o);
        if (lane >= o) x += y;
    }
    if (lane == 31) wsum[w] = x;
    __syncthreads();
    if (w == 0) {
        int s = wsum[lane];
        #pragma unroll
        for (int o = 1; o < 32; o <<= 1) {
            int y = __shfl_up_sync(0xffffffffu, s, o);
            if (lane >= o) s += y;
        }
        wsum[lane] = s;
    }
    __syncthreads();
    int incl = x + (w > 0 ? wsum[w - 1] : 0);
    g_rowptr[i] = incl;                 // inclusive-within-block (temp)
    if (t == 1023) g_bsum[b] = incl;
}

__global__ void k_scan2() {
    if (threadIdx.x == 0) {
        int s = 0;
        for (int b = 0; b < 64; b++) { int v = g_bsum[b]; g_bsum[b] = s; s += v; }
    }
}

__global__ void k_scan3() {
    int i = blockIdx.x * blockDim.x + threadIdx.x;
    if (i < NN) {
        int excl = g_rowptr[i] - g_cnt[i] + g_bsum[i >> 10];
        g_rowptr[i] = excl;
        g_wp[i] = excl;
    }
}

__global__ void k_scatter(const int* __restrict__ ei) {
    int e = blockIdx.x * blockDim.x + threadIdx.x;
    if (e < EE) {
        int s = ei[e], d = ei[EE + e];
        float nrm = -(g_dinv[s] * g_dinv[d]);
        int pos = atomicAdd(&g_wp[d], 1);
        g_edges[pos] = make_int2(s, __float_as_int(nrm));
    }
}

// ---------------- layer 1 (scalar features) ----------------
template <bool PREV>
__global__ void k_sprop(const float* __restrict__ sin,
                        const float* __restrict__ sprev,
                        float* __restrict__ sout) {
    int gw = (blockIdx.x * blockDim.x + threadIdx.x) >> 5;
    int lane = threadIdx.x & 31;
    int beg = g_rowptr[gw], c = g_cnt[gw];
    float acc = 0.0f;
    for (int j = lane; j < c; j += 32) {
        int2 ed = g_edges[beg + j];
        acc += __int_as_float(ed.y) * __ldg(&sin[ed.x]);
    }
    #pragma unroll
    for (int o = 16; o; o >>= 1) acc += __shfl_xor_sync(0xffffffffu, acc, o);
    if (lane == 0) sout[gw] = PREV ? (2.0f * acc - sprev[gw]) : acc;
}

// layer-1 combine + layer-2 init: h = relu(b1 + sum_k s_k * W1[k]); O = h @ W2[0]
__global__ void __launch_bounds__(256, 6) k_l1init(const float* __restrict__ x,
                                                   const float* __restrict__ W1,
                                                   const float* __restrict__ b1,
                                                   const float* __restrict__ W20) {
    __shared__ float Ws[1024];
    int tid = threadIdx.x;
    for (int j = tid; j < 1024; j += 256) Ws[j] = W20[j];
    __syncthreads();
    int gw = (blockIdx.x * 256 + tid) >> 5;
    int lane = tid & 31;
    float v = b1[lane]
            + x[gw]      * W1[lane]
            + g_s1[gw]   * W1[32 + lane]
            + g_s2[gw]   * W1[64 + lane]
            + g_s3[gw]   * W1[96 + lane]
            + g_s4[gw]   * W1[128 + lane];
    float h = fmaxf(v, 0.0f);
    g_H[gw * HID + lane] = h;
    float oacc = 0.0f;
    #pragma unroll
    for (int j = 0; j < 32; j++)
        oacc = fmaf(__shfl_sync(0xffffffffu, h, j), Ws[j * 32 + lane], oacc);
    g_O[gw * HID + lane] = oacc;
}

// ---------------- layers 2/3 (32-wide) ----------------
// fused: t_new = (PREV ? 2*prop(tin) - tprev : prop(tin));  tout = t_new;
//        g_O += t_new @ Wk   (W from smem to keep regs low -> high occupancy)
template <bool PREV>
__global__ void __launch_bounds__(256, 6) k_prop32(const float* __restrict__ tin,
                                                   const float* __restrict__ tprev,
                                                   float* __restrict__ tout,
                                                   const float* __restrict__ Wk) {
    __shared__ float Ws[1024];
    int tid = threadIdx.x;
    for (int j = tid; j < 1024; j += 256) Ws[j] = Wk[j];
    __syncthreads();
    int gw = (blockIdx.x * 256 + tid) >> 5;
    int lane = tid & 31;
    int beg = g_rowptr[gw], cnt = g_cnt[gw];
    float acc = 0.0f;
    for (int base = 0; base < cnt; base += 8) {
        #pragma unroll
        for (int jj = 0; jj < 8; jj++) {
            if (base + jj < cnt) {                       // uniform across warp
                int2 ed = g_edges[beg + base + jj];      // uniform (broadcast) load
                acc = fmaf(__int_as_float(ed.y),
                           __ldg(&tin[ed.x * HID + lane]), acc);
            }
        }
    }
    float tn = PREV ? (2.0f * acc - tprev[gw * HID + lane]) : acc;
    tout[gw * HID + lane] = tn;
    float oacc = g_O[gw * HID + lane];
    #pragma unroll
    for (int j = 0; j < 32; j++)
        oacc = fmaf(__shfl_sync(0xffffffffu, tn, j), Ws[j * 32 + lane], oacc);
    g_O[gw * HID + lane] = oacc;
}

// finalize layer L + init layer L+1: h = relu(O + b); H = h; O = h @ Wn0
__global__ void __launch_bounds__(256, 6) k_finit(const float* __restrict__ b,
                                                  const float* __restrict__ Wn0) {
    __shared__ float Ws[1024];
    int tid = threadIdx.x;
    for (int j = tid; j < 1024; j += 256) Ws[j] = Wn0[j];
    __syncthreads();
    int gw = (blockIdx.x * 256 + tid) >> 5;
    int lane = tid & 31;
    float h = fmaxf(g_O[gw * HID + lane] + b[lane], 0.0f);
    g_H[gw * HID + lane] = h;
    float oacc = 0.0f;
    #pragma unroll
    for (int j = 0; j < 32; j++)
        oacc = fmaf(__shfl_sync(0xffffffffu, h, j), Ws[j * 32 + lane], oacc);
    g_O[gw * HID + lane] = oacc;
}

// final layer bias (no relu, no next-layer init): H = O + b
__global__ void k_finalize(const float* __restrict__ b) {
    int i = blockIdx.x * blockDim.x + threadIdx.x;
    g_H[i] = g_O[i] + b[i & 31];
}

// ---------------- final linear: (8, 262144) @ (262144, 33) + bl ----------------
__global__ void k_obias(const float* __restrict__ bl, float* __restrict__ out) {
    int i = threadIdx.x;
    if (i < NG * OC) out[i] = bl[i % OC];
}

__global__ void __launch_bounds__(288) k_linear(const float* __restrict__ Wl,
                                                float* __restrict__ out) {
    __shared__ float Ws[128 * OC];   // 16896 B
    __shared__ float hs[NG * 128];   //  4096 B
    int t = threadIdx.x;
    int i0 = blockIdx.x * 128;
    for (int j = t; j < 128 * OC; j += 288) Ws[j] = Wl[i0 * OC + j];
    for (int j = t; j < NG * 128; j += 288) {
        int g = j >> 7, ii = j & 127;
        hs[j] = g_H[g * (ISZ * HID) + i0 + ii];
    }
    __syncthreads();
    if (t < NG * OC) {
        int g = t / OC, o = t % OC;
        float acc = 0.0f;
        #pragma unroll 8
        for (int ii = 0; ii < 128; ii++)
            acc = fmaf(hs[g * 128 + ii], Ws[ii * OC + o], acc);
        atomicAdd(&out[g * OC + o], acc);
    }
}

// ---------------- host ----------------
extern "C" void kernel_launch(void* const* d_in, const int* in_sizes, int n_in,
                              void* d_out, int out_size) {
    const float* x  = (const float*)d_in[0];
    const int*   ei = (const int*)  d_in[1];
    const float* W1 = (const float*)d_in[3];
    const float* b1 = (const float*)d_in[4];
    const float* W2 = (const float*)d_in[5];
    const float* b2 = (const float*)d_in[6];
    const float* W3 = (const float*)d_in[7];
    const float* b3 = (const float*)d_in[8];
    const float* Wl = (const float*)d_in[9];
    const float* bl = (const float*)d_in[10];
    float* out = (float*)d_out;

    float *dH, *dA, *dB, *dC, *dS1, *dS2, *dS3, *dS4;
    cudaGetSymbolAddress((void**)&dH,  g_H);
    cudaGetSymbolAddress((void**)&dA,  g_A);
    cudaGetSymbolAddress((void**)&dB,  g_B);
    cudaGetSymbolAddress((void**)&dC,  g_C);
    cudaGetSymbolAddress((void**)&dS1, g_s1);
    cudaGetSymbolAddress((void**)&dS2, g_s2);
    cudaGetSymbolAddress((void**)&dS3, g_s3);
    cudaGetSymbolAddress((void**)&dS4, g_s4);

    // CSR build
    k_zero   <<<NN / 256, 256>>>();
    k_hist   <<<EE / 256, 256>>>(ei);
    k_scan1  <<<64, 1024>>>();          // + fused dinv
    k_scan2  <<<1, 32>>>();
    k_scan3  <<<64, 1024>>>();
    k_scatter<<<EE / 256, 256>>>(ei);

    // layer 1 (scalar Chebyshev recurrence, then fused combine + layer-2 init)
    k_sprop<false><<<NN / 8, 256>>>(x,   nullptr, dS1);
    k_sprop<true> <<<NN / 8, 256>>>(dS1, x,       dS2);
    k_sprop<true> <<<NN / 8, 256>>>(dS2, dS1,     dS3);
    k_sprop<true> <<<NN / 8, 256>>>(dS3, dS2,     dS4);
    k_l1init<<<NN / 8, 256>>>(x, W1, b1, W2);

    // layer 2
    k_prop32<false> <<<NN / 8, 256>>>(dH, nullptr, dA, W2 + 1 * 1024);
    k_prop32<true>  <<<NN / 8, 256>>>(dA, dH,      dB, W2 + 2 * 1024);
    k_prop32<true>  <<<NN / 8, 256>>>(dB, dA,      dC, W2 + 3 * 1024);
    k_prop32<true>  <<<NN / 8, 256>>>(dC, dB,      dA, W2 + 4 * 1024);
    k_finit<<<NN / 8, 256>>>(b2, W3);   // relu + layer-3 init

    // layer 3
    k_prop32<false> <<<NN / 8, 256>>>(dH, nullptr, dA, W3 + 1 * 1024);
    k_prop32<true>  <<<NN / 8, 256>>>(dA, dH,      dB, W3 + 2 * 1024);
    k_prop32<true>  <<<NN / 8, 256>>>(dB, dA,      dC, W3 + 3 * 1024);
    k_prop32<true>  <<<NN / 8, 256>>>(dC, dB,      dA, W3 + 4 * 1024);
    k_finalize<<<NN * HID / 256, 256>>>(b3);

    // readout
    k_obias <<<1, 288>>>(bl, out);
    k_linear<<<(ISZ * HID) / 128, 288>>>(Wl, out);
}